// round 8
// baseline (speedup 1.0000x reference)
#include <cuda_runtime.h>

// IntShear4 (terminal form): M = S_{P-1} @ ... @ S_0, S_p = I + k_int[p] e_i e_j^T
// k_int = round-half-even(3*tanh(x)) == sign(x) * (#thresholds below |x|),
//   thresholds: atanh(1/6), atanh(1/2), atanh(5/6)  (3*tanh = 0.5, 1.5, 2.5).
// Left shear == row_i(M) += k * row_j(M): columns of M evolve independently.
//
// Lane p<P loads its triple, packs (k_int, i*4+j) into one int; one shuffle
// per step broadcasts it. Lanes 0..3 each own one column of M in registers.
// Single unrolled body; P<=12 handled by predicating each step (kk=0, code=0
// for lanes >= P is a no-op shear on column 0: m0 += 0*m0).

__global__ void intshear4_kernel(const float* __restrict__ k_raw,
                                 const int* __restrict__ pairs_i,
                                 const int* __restrict__ pairs_j,
                                 float* __restrict__ out,
                                 int P) {
    const int lane = threadIdx.x;

    int packed = 0;   // lanes >= P keep 0 -> k_int=0, i=j=0 -> identity shear
    if (lane < P) {
        float x  = __ldg(k_raw + lane);
        int   ii = __ldg(pairs_i + lane);
        int   jj = __ldg(pairs_j + lane);
        float ax = fabsf(x);
        int mag = (ax > 0.16823612f) + (ax > 0.54930614f) + (ax > 1.19894763f);
        int ki  = (x < 0.0f) ? -mag : mag;
        packed  = (ki << 8) | (ii * 4 + jj);
    }

    // Lane c in 0..3 owns column c of M; other lanes compute dead values.
    float m0 = (lane == 0) ? 1.0f : 0.0f;
    float m1 = (lane == 1) ? 1.0f : 0.0f;
    float m2 = (lane == 2) ? 1.0f : 0.0f;
    float m3 = (lane == 3) ? 1.0f : 0.0f;

    const int steps = (P < 12) ? P : 12;  // P is 12 in this problem
#pragma unroll
    for (int p = 0; p < 12; p++) {
        if (p < steps) {
            int   w  = __shfl_sync(0xFFFFFFFFu, packed, p);
            float kk = (float)(w >> 8);          // arithmetic shift: signed k_int
            int   jj = w & 3;
            int   ii = (w >> 2) & 3;
            float src = (jj == 0) ? m0 : (jj == 1) ? m1 : (jj == 2) ? m2 : m3;
            float add = kk * src;
            if      (ii == 0) m0 += add;
            else if (ii == 1) m1 += add;
            else if (ii == 2) m2 += add;
            else              m3 += add;
        }
    }

    if (lane < 4) {
        // out is row-major [4,4]; lane = column index
        out[0 * 4 + lane] = m0;
        out[1 * 4 + lane] = m1;
        out[2 * 4 + lane] = m2;
        out[3 * 4 + lane] = m3;
    }
}

extern "C" void kernel_launch(void* const* d_in, const int* in_sizes, int n_in,
                              void* d_out, int out_size) {
    const float* k_raw   = (const float*)d_in[0];
    const int*   pairs_i = (const int*)d_in[1];
    const int*   pairs_j = (const int*)d_in[2];
    float* out = (float*)d_out;
    int P = in_sizes[0];
    intshear4_kernel<<<1, 32>>>(k_raw, pairs_i, pairs_j, out, P);
}

// round 9
// speedup vs baseline: 1.0052x; 1.0052x over previous
#include <cuda_runtime.h>

// IntShear4 (final): M = S_{P-1} @ ... @ S_0, S_p = I + k_int[p] e_i e_j^T
// k_int = round-half-even(3*tanh(x)) == sign(x) * (#thresholds below |x|),
//   thresholds: atanh(1/6), atanh(1/2), atanh(5/6)  (3*tanh = 0.5, 1.5, 2.5).
// Left shear == row_i(M) += k * row_j(M): columns of M evolve independently.
//
// Lane p<P loads its triple and packs (k_int, i*4+j) into one int; one
// shuffle per step broadcasts it. Lanes 0..3 each own one column of M in
// registers. Single-launch, latency-floor-bound: measured wall time is the
// harness graph-replay floor (~6.2us); kernel work itself is <1us.

__global__ void __launch_bounds__(32, 1)
intshear4_kernel(const float* __restrict__ k_raw,
                 const int* __restrict__ pairs_i,
                 const int* __restrict__ pairs_j,
                 float* __restrict__ out,
                 int P) {
    const int lane = threadIdx.x;

    int packed = 0;   // lanes >= P: k_int=0, i=j=0 -> no-op shear (m0 += 0*m0)
    if (lane < P) {
        float x  = __ldg(k_raw + lane);
        int   ii = __ldg(pairs_i + lane);
        int   jj = __ldg(pairs_j + lane);
        float ax = fabsf(x);
        int mag = (ax > 0.16823612f) + (ax > 0.54930614f) + (ax > 1.19894763f);
        int ki  = (x < 0.0f) ? -mag : mag;
        packed  = (ki << 8) | (ii * 4 + jj);
    }

    // Lane c in 0..3 owns column c of M; other lanes compute dead values.
    float m0 = (lane == 0) ? 1.0f : 0.0f;
    float m1 = (lane == 1) ? 1.0f : 0.0f;
    float m2 = (lane == 2) ? 1.0f : 0.0f;
    float m3 = (lane == 3) ? 1.0f : 0.0f;

    if (P == 12) {
#pragma unroll
        for (int p = 0; p < 12; p++) {
            int   w  = __shfl_sync(0xFFFFFFFFu, packed, p);
            float kk = (float)(w >> 8);          // arithmetic shift: signed k_int
            int   jj = w & 3;
            int   ii = (w >> 2) & 3;
            float src = (jj == 0) ? m0 : (jj == 1) ? m1 : (jj == 2) ? m2 : m3;
            float add = kk * src;
            if      (ii == 0) m0 += add;
            else if (ii == 1) m1 += add;
            else if (ii == 2) m2 += add;
            else              m3 += add;
        }
    } else {
        for (int p = 0; p < P; p++) {
            int   w  = __shfl_sync(0xFFFFFFFFu, packed, p);
            float kk = (float)(w >> 8);
            int   jj = w & 3;
            int   ii = (w >> 2) & 3;
            float src = (jj == 0) ? m0 : (jj == 1) ? m1 : (jj == 2) ? m2 : m3;
            float add = kk * src;
            if      (ii == 0) m0 += add;
            else if (ii == 1) m1 += add;
            else if (ii == 2) m2 += add;
            else              m3 += add;
        }
    }

    if (lane < 4) {
        // out is row-major [4,4]; lane = column index
        out[0 * 4 + lane] = m0;
        out[1 * 4 + lane] = m1;
        out[2 * 4 + lane] = m2;
        out[3 * 4 + lane] = m3;
    }
}

extern "C" void kernel_launch(void* const* d_in, const int* in_sizes, int n_in,
                              void* d_out, int out_size) {
    const float* k_raw   = (const float*)d_in[0];
    const int*   pairs_i = (const int*)d_in[1];
    const int*   pairs_j = (const int*)d_in[2];
    float* out = (float*)d_out;
    int P = in_sizes[0];
    intshear4_kernel<<<1, 32>>>(k_raw, pairs_i, pairs_j, out, P);
}

// round 10
// speedup vs baseline: 1.0212x; 1.0159x over previous
#include <cuda_runtime.h>

// IntShear4 (final): M = S_{P-1} @ ... @ S_0, S_p = I + k_int[p] e_i e_j^T
// k_int = round-half-even(3*tanh(x)) == sign(x) * (#thresholds below |x|),
//   thresholds: atanh(1/6), atanh(1/2), atanh(5/6)  (3*tanh = 0.5, 1.5, 2.5).
// Left shear == row_i(M) += k * row_j(M): columns of M evolve independently.
//
// Lane p<P loads its triple and packs (k_int, i*4+j) into one int; one
// shuffle per step broadcasts it. Lanes 0..3 each own one column of M in
// registers. Single-launch, latency-floor-bound: measured wall time is the
// harness graph-replay floor (~6.15us); kernel work itself is <1us.

__global__ void __launch_bounds__(32, 1)
intshear4_kernel(const float* __restrict__ k_raw,
                 const int* __restrict__ pairs_i,
                 const int* __restrict__ pairs_j,
                 float* __restrict__ out,
                 int P) {
    const int lane = threadIdx.x;

    int packed = 0;   // lanes >= P: k_int=0, i=j=0 -> no-op shear (m0 += 0*m0)
    if (lane < P) {
        float x  = __ldg(k_raw + lane);
        int   ii = __ldg(pairs_i + lane);
        int   jj = __ldg(pairs_j + lane);
        float ax = fabsf(x);
        int mag = (ax > 0.16823612f) + (ax > 0.54930614f) + (ax > 1.19894763f);
        int ki  = (x < 0.0f) ? -mag : mag;
        packed  = (ki << 8) | (ii * 4 + jj);
    }

    // Lane c in 0..3 owns column c of M; other lanes compute dead values.
    float m0 = (lane == 0) ? 1.0f : 0.0f;
    float m1 = (lane == 1) ? 1.0f : 0.0f;
    float m2 = (lane == 2) ? 1.0f : 0.0f;
    float m3 = (lane == 3) ? 1.0f : 0.0f;

    if (P == 12) {
#pragma unroll
        for (int p = 0; p < 12; p++) {
            int   w  = __shfl_sync(0xFFFFFFFFu, packed, p);
            float kk = (float)(w >> 8);          // arithmetic shift: signed k_int
            int   jj = w & 3;
            int   ii = (w >> 2) & 3;
            float src = (jj == 0) ? m0 : (jj == 1) ? m1 : (jj == 2) ? m2 : m3;
            float add = kk * src;
            if      (ii == 0) m0 += add;
            else if (ii == 1) m1 += add;
            else if (ii == 2) m2 += add;
            else              m3 += add;
        }
    } else {
        for (int p = 0; p < P; p++) {
            int   w  = __shfl_sync(0xFFFFFFFFu, packed, p);
            float kk = (float)(w >> 8);
            int   jj = w & 3;
            int   ii = (w >> 2) & 3;
            float src = (jj == 0) ? m0 : (jj == 1) ? m1 : (jj == 2) ? m2 : m3;
            float add = kk * src;
            if      (ii == 0) m0 += add;
            else if (ii == 1) m1 += add;
            else if (ii == 2) m2 += add;
            else              m3 += add;
        }
    }

    if (lane < 4) {
        // out is row-major [4,4]; lane = column index
        out[0 * 4 + lane] = m0;
        out[1 * 4 + lane] = m1;
        out[2 * 4 + lane] = m2;
        out[3 * 4 + lane] = m3;
    }
}

extern "C" void kernel_launch(void* const* d_in, const int* in_sizes, int n_in,
                              void* d_out, int out_size) {
    const float* k_raw   = (const float*)d_in[0];
    const int*   pairs_i = (const int*)d_in[1];
    const int*   pairs_j = (const int*)d_in[2];
    float* out = (float*)d_out;
    int P = in_sizes[0];
    intshear4_kernel<<<1, 32>>>(k_raw, pairs_i, pairs_j, out, P);
}